// round 9
// baseline (speedup 1.0000x reference)
#include <cuda_runtime.h>

// Problem shape (fixed by reference): B=4, T=2048, N=1024, H=16, Dh=64
#define B_SZ   4
#define T_SEQ  2048
#define NDIM   1024
#define NH     16
#define DH     64
#define BH_TOT (B_SZ * NH)          // 64
#define M_ROWS (B_SZ * T_SEQ)       // 8192
#define K_DIM  1024

// Scratch (device globals — allocation-free per harness rules). 128 MB total.
__device__ float g_Q[(size_t)BH_TOT * T_SEQ * DH];   // [bh][t][d]
__device__ float g_K[(size_t)BH_TOT * T_SEQ * DH];
__device__ float g_V[(size_t)BH_TOT * T_SEQ * DH];
__device__ float g_Y[(size_t)M_ROWS * NDIM];         // attention output [b*T+t][n]

// ---------------------------------------------------------------------------
// SGEMM: C[M=8192, N] = A[8192,1024] @ W[1024,N] + bias
// MODE 0: A = param, epilogue scatters into g_Q/g_K/g_V ([bh][t][d] layout)
// MODE 1: A = g_Y,  epilogue writes Cout row-major
// 128x128 tile, BK=16, 256 threads, 8x8 micro-tile.
// ---------------------------------------------------------------------------
template <int N, int MODE>
__global__ __launch_bounds__(256, 2)
void sgemm_kernel(const float* __restrict__ A, const float* __restrict__ W,
                  const float* __restrict__ bias, float* __restrict__ Cout)
{
    __shared__ float As[16][128];   // [k][m]
    __shared__ float Bs[16][128];   // [k][n]

    const int tid  = threadIdx.x;
    const int row0 = blockIdx.y * 128;
    const int col0 = blockIdx.x * 128;

    const int aRow = tid >> 2;            // 0..63
    const int aCol = (tid & 3) << 2;      // 0,4,8,12
    const int bRow = tid >> 5;            // 0..7
    const int bCol = (tid & 31) << 2;     // 0..124

    const int ty = tid >> 4;              // 0..15
    const int tx = tid & 15;              // 0..15

    const float* Asrc = (MODE == 0) ? A : (const float*)g_Y;

    float acc[8][8];
#pragma unroll
    for (int i = 0; i < 8; i++)
#pragma unroll
        for (int j = 0; j < 8; j++) acc[i][j] = 0.f;

    const float* Ab = Asrc + (size_t)row0 * K_DIM;
    const float* Wb = W + col0;

    for (int k0 = 0; k0 < K_DIM; k0 += 16) {
#pragma unroll
        for (int i = 0; i < 2; i++) {
            int r = aRow + i * 64;
            float4 v = *(const float4*)(Ab + (size_t)r * K_DIM + (k0 + aCol));
            As[aCol + 0][r] = v.x;
            As[aCol + 1][r] = v.y;
            As[aCol + 2][r] = v.z;
            As[aCol + 3][r] = v.w;
        }
#pragma unroll
        for (int i = 0; i < 2; i++) {
            int r = bRow + i * 8;
            *(float4*)&Bs[r][bCol] = *(const float4*)(Wb + (size_t)(k0 + r) * N + bCol);
        }
        __syncthreads();

#pragma unroll
        for (int kk = 0; kk < 16; kk++) {
            float regM[8], regN[8];
            *(float4*)&regM[0] = *(float4*)&As[kk][ty * 8];
            *(float4*)&regM[4] = *(float4*)&As[kk][ty * 8 + 4];
            *(float4*)&regN[0] = *(float4*)&Bs[kk][tx * 8];
            *(float4*)&regN[4] = *(float4*)&Bs[kk][tx * 8 + 4];
#pragma unroll
            for (int i = 0; i < 8; i++)
#pragma unroll
                for (int j = 0; j < 8; j++)
                    acc[i][j] = fmaf(regM[i], regN[j], acc[i][j]);
        }
        __syncthreads();
    }

    float bv[8];
#pragma unroll
    for (int j = 0; j < 8; j++) bv[j] = bias[col0 + tx * 8 + j];

    if (MODE == 0) {
        // scatter qkv -> g_Q/g_K/g_V in [bh][t][d]
#pragma unroll
        for (int i = 0; i < 8; i++) {
            int r = row0 + ty * 8 + i;
            int b = r >> 11;           // /2048
            int t = r & 2047;
#pragma unroll
            for (int j = 0; j < 8; j++) {
                int c = col0 + tx * 8 + j;
                float v = acc[i][j] + bv[j];
                int which = c >> 10;   // 0=Q 1=K 2=V (uniform per CTA)
                int n = c & 1023;
                int h = n >> 6;
                int d = n & 63;
                size_t idx = (((size_t)(b * NH + h) * T_SEQ) + t) * DH + d;
                float* dst = (which == 0) ? g_Q : (which == 1) ? g_K : g_V;
                dst[idx] = v;
            }
        }
    } else {
#pragma unroll
        for (int i = 0; i < 8; i++) {
            size_t r = row0 + ty * 8 + i;
#pragma unroll
            for (int j = 0; j < 8; j++) {
                int c = col0 + tx * 8 + j;
                Cout[r * N + c] = acc[i][j] + bv[j];
            }
        }
    }
}

// ---------------------------------------------------------------------------
// Causal flash attention, fp32. One CTA per (bh, 64-query tile).
// 256 threads: ty=tid/16 owns 4 query rows, tx=tid%16 owns 4 cols.
// Online softmax; key blocks of 64 up to the causal limit.
// Dynamic smem: Qt[64][68] (d-major), Kt[64][68] (d-major), Vs[64][68], Pt[64][68]
// ---------------------------------------------------------------------------
#define APAD 68
#define ABUF (DH * APAD)                           // floats per buffer
#define ATTN_SMEM (4 * ABUF * (int)sizeof(float))  // 69632 bytes

__global__ __launch_bounds__(256, 3)
void attn_kernel()
{
    extern __shared__ float smem[];
    float* Qt = smem;               // [d][q]
    float* Kt = smem + ABUF;        // [d][k]
    float* Vs = smem + 2 * ABUF;    // [k][d]
    float* Pt = smem + 3 * ABUF;    // [k][q]

    const int tid = threadIdx.x;
    const int qb  = blockIdx.x;     // 0..31
    const int bh  = blockIdx.y;     // 0..63
    const int q0  = qb * 64;

    const float* Qg = g_Q + (size_t)bh * T_SEQ * DH;
    const float* Kg = g_K + (size_t)bh * T_SEQ * DH;
    const float* Vg = g_V + (size_t)bh * T_SEQ * DH;

    // Load Q tile transposed, pre-scaled by 1/sqrt(Dh)=0.125
#pragma unroll
    for (int it = 0; it < 4; it++) {
        int s   = tid + it * 256;    // float4 slot 0..1023
        int row = s >> 4;            // query 0..63
        int c4  = (s & 15) << 2;     // dim 0..60
        float4 v = *(const float4*)(Qg + (size_t)(q0 + row) * DH + c4);
        Qt[(c4 + 0) * APAD + row] = v.x * 0.125f;
        Qt[(c4 + 1) * APAD + row] = v.y * 0.125f;
        Qt[(c4 + 2) * APAD + row] = v.z * 0.125f;
        Qt[(c4 + 3) * APAD + row] = v.w * 0.125f;
    }

    const int ty = tid >> 4;   // q rows ty*4..+4
    const int tx = tid & 15;   // cols tx*4..+4

    float acc[4][4];
    float mrow[4], lrow[4];
#pragma unroll
    for (int i = 0; i < 4; i++) {
        mrow[i] = -1e30f;
        lrow[i] = 0.f;
#pragma unroll
        for (int j = 0; j < 4; j++) acc[i][j] = 0.f;
    }

    for (int jb = 0; jb <= qb; jb++) {
        const int k0 = jb * 64;
        __syncthreads();   // previous PV (reads Vs/Pt) done before reload
#pragma unroll
        for (int it = 0; it < 4; it++) {
            int s   = tid + it * 256;
            int row = s >> 4;
            int c4  = (s & 15) << 2;
            float4 kv = *(const float4*)(Kg + (size_t)(k0 + row) * DH + c4);
            Kt[(c4 + 0) * APAD + row] = kv.x;
            Kt[(c4 + 1) * APAD + row] = kv.y;
            Kt[(c4 + 2) * APAD + row] = kv.z;
            Kt[(c4 + 3) * APAD + row] = kv.w;
            *(float4*)&Vs[row * APAD + c4] =
                *(const float4*)(Vg + (size_t)(k0 + row) * DH + c4);
        }
        __syncthreads();

        // S[4q][4k] = Q K^T (scale already folded into Q)
        float S[4][4];
#pragma unroll
        for (int i = 0; i < 4; i++)
#pragma unroll
            for (int j = 0; j < 4; j++) S[i][j] = 0.f;

#pragma unroll 16
        for (int d = 0; d < DH; d++) {
            float4 qv = *(float4*)&Qt[d * APAD + ty * 4];
            float4 kv = *(float4*)&Kt[d * APAD + tx * 4];
            float qr[4] = {qv.x, qv.y, qv.z, qv.w};
            float kr[4] = {kv.x, kv.y, kv.z, kv.w};
#pragma unroll
            for (int i = 0; i < 4; i++)
#pragma unroll
                for (int j = 0; j < 4; j++)
                    S[i][j] = fmaf(qr[i], kr[j], S[i][j]);
        }

        if (jb == qb) {   // diagonal block: causal mask
#pragma unroll
            for (int i = 0; i < 4; i++)
#pragma unroll
                for (int j = 0; j < 4; j++)
                    if ((k0 + tx * 4 + j) > (q0 + ty * 4 + i)) S[i][j] = -1e30f;
        }

        // Online softmax. Row = 16 threads (same ty) = one 16-lane shfl segment.
#pragma unroll
        for (int i = 0; i < 4; i++) {
            float m = fmaxf(fmaxf(S[i][0], S[i][1]), fmaxf(S[i][2], S[i][3]));
            m = fmaxf(m, __shfl_xor_sync(0xffffffffu, m, 8));
            m = fmaxf(m, __shfl_xor_sync(0xffffffffu, m, 4));
            m = fmaxf(m, __shfl_xor_sync(0xffffffffu, m, 2));
            m = fmaxf(m, __shfl_xor_sync(0xffffffffu, m, 1));
            float mnew = fmaxf(mrow[i], m);
            float corr = __expf(mrow[i] - mnew);
            mrow[i] = mnew;

            float ls = 0.f;
#pragma unroll
            for (int j = 0; j < 4; j++) {
                float p = __expf(S[i][j] - mnew);
                S[i][j] = p;
                ls += p;
            }
            ls += __shfl_xor_sync(0xffffffffu, ls, 8);
            ls += __shfl_xor_sync(0xffffffffu, ls, 4);
            ls += __shfl_xor_sync(0xffffffffu, ls, 2);
            ls += __shfl_xor_sync(0xffffffffu, ls, 1);
            lrow[i] = lrow[i] * corr + ls;

#pragma unroll
            for (int j = 0; j < 4; j++) {
                acc[i][j] *= corr;
                Pt[(tx * 4 + j) * APAD + ty * 4 + i] = S[i][j];
            }
        }
        __syncthreads();

        // O[4q][4d] += P @ V
#pragma unroll 16
        for (int k = 0; k < 64; k++) {
            float4 pv = *(float4*)&Pt[k * APAD + ty * 4];
            float4 vv = *(float4*)&Vs[k * APAD + tx * 4];
            float pr[4] = {pv.x, pv.y, pv.z, pv.w};
            float vr[4] = {vv.x, vv.y, vv.z, vv.w};
#pragma unroll
            for (int i = 0; i < 4; i++)
#pragma unroll
                for (int j = 0; j < 4; j++)
                    acc[i][j] = fmaf(pr[i], vr[j], acc[i][j]);
        }
    }

    // Epilogue: y[b][t][h*64+d] = acc / l
    const int b = bh >> 4;
    const int h = bh & 15;
#pragma unroll
    for (int i = 0; i < 4; i++) {
        float inv = 1.f / lrow[i];
        size_t t = (size_t)q0 + ty * 4 + i;
#pragma unroll
        for (int j = 0; j < 4; j++) {
            g_Y[((size_t)b * T_SEQ + t) * NDIM + h * DH + tx * 4 + j] =
                acc[i][j] * inv;
        }
    }
}

// ---------------------------------------------------------------------------
extern "C" void kernel_launch(void* const* d_in, const int* in_sizes, int n_in,
                              void* d_out, int out_size)
{
    (void)in_sizes; (void)n_in; (void)out_size;
    const float* x      = (const float*)d_in[0];   // [4,2048,1024]
    const float* W_attn = (const float*)d_in[1];   // [1024,3072]
    const float* b_attn = (const float*)d_in[2];   // [3072]
    const float* W_proj = (const float*)d_in[3];   // [1024,1024]
    const float* b_proj = (const float*)d_in[4];   // [1024]
    float* out = (float*)d_out;                    // [4,2048,1024]

    // Host-side attribute set (not a stream op — capture-safe, idempotent)
    cudaFuncSetAttribute(attn_kernel,
                         cudaFuncAttributeMaxDynamicSharedMemorySize, ATTN_SMEM);

    // 1) QKV GEMM + scatter to [bh][t][d]
    sgemm_kernel<3072, 0><<<dim3(3072 / 128, M_ROWS / 128), 256>>>(
        x, W_attn, b_attn, nullptr);

    // 2) Causal flash attention
    attn_kernel<<<dim3(T_SEQ / 64, BH_TOT), 256, ATTN_SMEM>>>();

    // 3) Output projection
    sgemm_kernel<1024, 1><<<dim3(1024 / 128, M_ROWS / 128), 256>>>(
        nullptr, W_proj, b_proj, out);
}

// round 10
// speedup vs baseline: 1.0090x; 1.0090x over previous
#include <cuda_runtime.h>

// Problem shape (fixed by reference): B=4, T=2048, N=1024, H=16, Dh=64
#define B_SZ   4
#define T_SEQ  2048
#define NDIM   1024
#define NH     16
#define DH     64
#define BH_TOT (B_SZ * NH)          // 64
#define M_ROWS (B_SZ * T_SEQ)       // 8192
#define K_DIM  1024

// Scratch (device globals — allocation-free per harness rules). 128 MB total.
__device__ float g_Q[(size_t)BH_TOT * T_SEQ * DH];   // [bh][t][d]
__device__ float g_K[(size_t)BH_TOT * T_SEQ * DH];
__device__ float g_V[(size_t)BH_TOT * T_SEQ * DH];
__device__ float g_Y[(size_t)M_ROWS * NDIM];         // attention output [b*T+t][n]

// ---------------------------------------------------------------------------
// SGEMM: C[M=8192, N] = A[8192,1024] @ W[1024,N] + bias
// MODE 0: A = param, epilogue scatters into g_Q/g_K/g_V ([bh][t][d] layout)
// MODE 1: A = g_Y,  epilogue writes Cout row-major
// 128x128 tile, BK=16, 256 threads, 8x8 micro-tile.
// ---------------------------------------------------------------------------
template <int N, int MODE>
__global__ __launch_bounds__(256, 2)
void sgemm_kernel(const float* __restrict__ A, const float* __restrict__ W,
                  const float* __restrict__ bias, float* __restrict__ Cout)
{
    __shared__ float As[16][128];   // [k][m]
    __shared__ float Bs[16][128];   // [k][n]

    const int tid  = threadIdx.x;
    const int row0 = blockIdx.y * 128;
    const int col0 = blockIdx.x * 128;

    const int aRow = tid >> 2;            // 0..63
    const int aCol = (tid & 3) << 2;      // 0,4,8,12
    const int bRow = tid >> 5;            // 0..7
    const int bCol = (tid & 31) << 2;     // 0..124

    const int ty = tid >> 4;              // 0..15
    const int tx = tid & 15;              // 0..15

    const float* Asrc = (MODE == 0) ? A : (const float*)g_Y;

    float acc[8][8];
#pragma unroll
    for (int i = 0; i < 8; i++)
#pragma unroll
        for (int j = 0; j < 8; j++) acc[i][j] = 0.f;

    const float* Ab = Asrc + (size_t)row0 * K_DIM;
    const float* Wb = W + col0;

    for (int k0 = 0; k0 < K_DIM; k0 += 16) {
#pragma unroll
        for (int i = 0; i < 2; i++) {
            int r = aRow + i * 64;
            float4 v = *(const float4*)(Ab + (size_t)r * K_DIM + (k0 + aCol));
            As[aCol + 0][r] = v.x;
            As[aCol + 1][r] = v.y;
            As[aCol + 2][r] = v.z;
            As[aCol + 3][r] = v.w;
        }
#pragma unroll
        for (int i = 0; i < 2; i++) {
            int r = bRow + i * 8;
            *(float4*)&Bs[r][bCol] = *(const float4*)(Wb + (size_t)(k0 + r) * N + bCol);
        }
        __syncthreads();

#pragma unroll
        for (int kk = 0; kk < 16; kk++) {
            float regM[8], regN[8];
            *(float4*)&regM[0] = *(float4*)&As[kk][ty * 8];
            *(float4*)&regM[4] = *(float4*)&As[kk][ty * 8 + 4];
            *(float4*)&regN[0] = *(float4*)&Bs[kk][tx * 8];
            *(float4*)&regN[4] = *(float4*)&Bs[kk][tx * 8 + 4];
#pragma unroll
            for (int i = 0; i < 8; i++)
#pragma unroll
                for (int j = 0; j < 8; j++)
                    acc[i][j] = fmaf(regM[i], regN[j], acc[i][j]);
        }
        __syncthreads();
    }

    float bv[8];
#pragma unroll
    for (int j = 0; j < 8; j++) bv[j] = bias[col0 + tx * 8 + j];

    if (MODE == 0) {
        // scatter qkv -> g_Q/g_K/g_V in [bh][t][d]
#pragma unroll
        for (int i = 0; i < 8; i++) {
            int r = row0 + ty * 8 + i;
            int b = r >> 11;           // /2048
            int t = r & 2047;
#pragma unroll
            for (int j = 0; j < 8; j++) {
                int c = col0 + tx * 8 + j;
                float v = acc[i][j] + bv[j];
                int which = c >> 10;   // 0=Q 1=K 2=V (uniform per CTA)
                int n = c & 1023;
                int h = n >> 6;
                int d = n & 63;
                size_t idx = (((size_t)(b * NH + h) * T_SEQ) + t) * DH + d;
                float* dst = (which == 0) ? g_Q : (which == 1) ? g_K : g_V;
                dst[idx] = v;
            }
        }
    } else {
#pragma unroll
        for (int i = 0; i < 8; i++) {
            size_t r = row0 + ty * 8 + i;
#pragma unroll
            for (int j = 0; j < 8; j++) {
                int c = col0 + tx * 8 + j;
                Cout[r * N + c] = acc[i][j] + bv[j];
            }
        }
    }
}

// ---------------------------------------------------------------------------
// Causal flash attention, fp32. One CTA per (bh, 64-query tile).
// 256 threads: ty=tid/16 owns 4 query rows, tx=tid%16 owns 4 cols.
// Online softmax; key blocks of 64 up to the causal limit.
// Dynamic smem: Qt[64][68] (d-major), Kt[64][68] (d-major), Vs[64][68], Pt[64][68]
// ---------------------------------------------------------------------------
#define APAD 68
#define ABUF (DH * APAD)                           // floats per buffer
#define ATTN_SMEM (4 * ABUF * (int)sizeof(float))  // 69632 bytes

__global__ __launch_bounds__(256, 3)
void attn_kernel()
{
    extern __shared__ float smem[];
    float* Qt = smem;               // [d][q]
    float* Kt = smem + ABUF;        // [d][k]
    float* Vs = smem + 2 * ABUF;    // [k][d]
    float* Pt = smem + 3 * ABUF;    // [k][q]

    const int tid = threadIdx.x;
    const int qb  = blockIdx.x;     // 0..31
    const int bh  = blockIdx.y;     // 0..63
    const int q0  = qb * 64;

    const float* Qg = g_Q + (size_t)bh * T_SEQ * DH;
    const float* Kg = g_K + (size_t)bh * T_SEQ * DH;
    const float* Vg = g_V + (size_t)bh * T_SEQ * DH;

    // Load Q tile transposed, pre-scaled by 1/sqrt(Dh)=0.125
#pragma unroll
    for (int it = 0; it < 4; it++) {
        int s   = tid + it * 256;    // float4 slot 0..1023
        int row = s >> 4;            // query 0..63
        int c4  = (s & 15) << 2;     // dim 0..60
        float4 v = *(const float4*)(Qg + (size_t)(q0 + row) * DH + c4);
        Qt[(c4 + 0) * APAD + row] = v.x * 0.125f;
        Qt[(c4 + 1) * APAD + row] = v.y * 0.125f;
        Qt[(c4 + 2) * APAD + row] = v.z * 0.125f;
        Qt[(c4 + 3) * APAD + row] = v.w * 0.125f;
    }

    const int ty = tid >> 4;   // q rows ty*4..+4
    const int tx = tid & 15;   // cols tx*4..+4

    float acc[4][4];
    float mrow[4], lrow[4];
#pragma unroll
    for (int i = 0; i < 4; i++) {
        mrow[i] = -1e30f;
        lrow[i] = 0.f;
#pragma unroll
        for (int j = 0; j < 4; j++) acc[i][j] = 0.f;
    }

    for (int jb = 0; jb <= qb; jb++) {
        const int k0 = jb * 64;
        __syncthreads();   // previous PV (reads Vs/Pt) done before reload
#pragma unroll
        for (int it = 0; it < 4; it++) {
            int s   = tid + it * 256;
            int row = s >> 4;
            int c4  = (s & 15) << 2;
            float4 kv = *(const float4*)(Kg + (size_t)(k0 + row) * DH + c4);
            Kt[(c4 + 0) * APAD + row] = kv.x;
            Kt[(c4 + 1) * APAD + row] = kv.y;
            Kt[(c4 + 2) * APAD + row] = kv.z;
            Kt[(c4 + 3) * APAD + row] = kv.w;
            *(float4*)&Vs[row * APAD + c4] =
                *(const float4*)(Vg + (size_t)(k0 + row) * DH + c4);
        }
        __syncthreads();

        // S[4q][4k] = Q K^T (scale already folded into Q)
        float S[4][4];
#pragma unroll
        for (int i = 0; i < 4; i++)
#pragma unroll
            for (int j = 0; j < 4; j++) S[i][j] = 0.f;

#pragma unroll 16
        for (int d = 0; d < DH; d++) {
            float4 qv = *(float4*)&Qt[d * APAD + ty * 4];
            float4 kv = *(float4*)&Kt[d * APAD + tx * 4];
            float qr[4] = {qv.x, qv.y, qv.z, qv.w};
            float kr[4] = {kv.x, kv.y, kv.z, kv.w};
#pragma unroll
            for (int i = 0; i < 4; i++)
#pragma unroll
                for (int j = 0; j < 4; j++)
                    S[i][j] = fmaf(qr[i], kr[j], S[i][j]);
        }

        if (jb == qb) {   // diagonal block: causal mask
#pragma unroll
            for (int i = 0; i < 4; i++)
#pragma unroll
                for (int j = 0; j < 4; j++)
                    if ((k0 + tx * 4 + j) > (q0 + ty * 4 + i)) S[i][j] = -1e30f;
        }

        // Online softmax. Row = 16 threads (same ty) = one 16-lane shfl segment.
#pragma unroll
        for (int i = 0; i < 4; i++) {
            float m = fmaxf(fmaxf(S[i][0], S[i][1]), fmaxf(S[i][2], S[i][3]));
            m = fmaxf(m, __shfl_xor_sync(0xffffffffu, m, 8));
            m = fmaxf(m, __shfl_xor_sync(0xffffffffu, m, 4));
            m = fmaxf(m, __shfl_xor_sync(0xffffffffu, m, 2));
            m = fmaxf(m, __shfl_xor_sync(0xffffffffu, m, 1));
            float mnew = fmaxf(mrow[i], m);
            float corr = __expf(mrow[i] - mnew);
            mrow[i] = mnew;

            float ls = 0.f;
#pragma unroll
            for (int j = 0; j < 4; j++) {
                float p = __expf(S[i][j] - mnew);
                S[i][j] = p;
                ls += p;
            }
            ls += __shfl_xor_sync(0xffffffffu, ls, 8);
            ls += __shfl_xor_sync(0xffffffffu, ls, 4);
            ls += __shfl_xor_sync(0xffffffffu, ls, 2);
            ls += __shfl_xor_sync(0xffffffffu, ls, 1);
            lrow[i] = lrow[i] * corr + ls;

#pragma unroll
            for (int j = 0; j < 4; j++) {
                acc[i][j] *= corr;
                Pt[(tx * 4 + j) * APAD + ty * 4 + i] = S[i][j];
            }
        }
        __syncthreads();

        // O[4q][4d] += P @ V
#pragma unroll 16
        for (int k = 0; k < 64; k++) {
            float4 pv = *(float4*)&Pt[k * APAD + ty * 4];
            float4 vv = *(float4*)&Vs[k * APAD + tx * 4];
            float pr[4] = {pv.x, pv.y, pv.z, pv.w};
            float vr[4] = {vv.x, vv.y, vv.z, vv.w};
#pragma unroll
            for (int i = 0; i < 4; i++)
#pragma unroll
                for (int j = 0; j < 4; j++)
                    acc[i][j] = fmaf(pr[i], vr[j], acc[i][j]);
        }
    }

    // Epilogue: y[b][t][h*64+d] = acc / l
    const int b = bh >> 4;
    const int h = bh & 15;
#pragma unroll
    for (int i = 0; i < 4; i++) {
        float inv = 1.f / lrow[i];
        size_t t = (size_t)q0 + ty * 4 + i;
#pragma unroll
        for (int j = 0; j < 4; j++) {
            g_Y[((size_t)b * T_SEQ + t) * NDIM + h * DH + tx * 4 + j] =
                acc[i][j] * inv;
        }
    }
}

// ---------------------------------------------------------------------------
extern "C" void kernel_launch(void* const* d_in, const int* in_sizes, int n_in,
                              void* d_out, int out_size)
{
    (void)in_sizes; (void)n_in; (void)out_size;
    const float* x      = (const float*)d_in[0];   // [4,2048,1024]
    const float* W_attn = (const float*)d_in[1];   // [1024,3072]
    const float* b_attn = (const float*)d_in[2];   // [3072]
    const float* W_proj = (const float*)d_in[3];   // [1024,1024]
    const float* b_proj = (const float*)d_in[4];   // [1024]
    float* out = (float*)d_out;                    // [4,2048,1024]

    // Host-side attribute set (not a stream op — capture-safe, idempotent)
    cudaFuncSetAttribute(attn_kernel,
                         cudaFuncAttributeMaxDynamicSharedMemorySize, ATTN_SMEM);

    // 1) QKV GEMM + scatter to [bh][t][d]
    sgemm_kernel<3072, 0><<<dim3(3072 / 128, M_ROWS / 128), 256>>>(
        x, W_attn, b_attn, nullptr);

    // 2) Causal flash attention
    attn_kernel<<<dim3(T_SEQ / 64, BH_TOT), 256, ATTN_SMEM>>>();

    // 3) Output projection
    sgemm_kernel<1024, 1><<<dim3(1024 / 128, M_ROWS / 128), 256>>>(
        nullptr, W_proj, b_proj, out);
}

// round 11
// speedup vs baseline: 1.0099x; 1.0009x over previous
#include <cuda_runtime.h>

// Problem shape (fixed by reference): B=4, T=2048, N=1024, H=16, Dh=64
#define B_SZ   4
#define T_SEQ  2048
#define NDIM   1024
#define NH     16
#define DH     64
#define BH_TOT (B_SZ * NH)          // 64
#define M_ROWS (B_SZ * T_SEQ)       // 8192
#define K_DIM  1024

// Scratch (device globals — allocation-free per harness rules). 128 MB total.
__device__ float g_Q[(size_t)BH_TOT * T_SEQ * DH];   // [bh][t][d]
__device__ float g_K[(size_t)BH_TOT * T_SEQ * DH];
__device__ float g_V[(size_t)BH_TOT * T_SEQ * DH];
__device__ float g_Y[(size_t)M_ROWS * NDIM];         // attention output [b*T+t][n]

// ---------------------------------------------------------------------------
// SGEMM: C[M=8192, N] = A[8192,1024] @ W[1024,N] + bias
// MODE 0: A = param, epilogue scatters into g_Q/g_K/g_V ([bh][t][d] layout)
// MODE 1: A = g_Y,  epilogue writes Cout row-major
// 128x128 tile, BK=16, 256 threads, 8x8 micro-tile.
// ---------------------------------------------------------------------------
template <int N, int MODE>
__global__ __launch_bounds__(256, 2)
void sgemm_kernel(const float* __restrict__ A, const float* __restrict__ W,
                  const float* __restrict__ bias, float* __restrict__ Cout)
{
    __shared__ float As[16][128];   // [k][m]
    __shared__ float Bs[16][128];   // [k][n]

    const int tid  = threadIdx.x;
    const int row0 = blockIdx.y * 128;
    const int col0 = blockIdx.x * 128;

    const int aRow = tid >> 2;            // 0..63
    const int aCol = (tid & 3) << 2;      // 0,4,8,12
    const int bRow = tid >> 5;            // 0..7
    const int bCol = (tid & 31) << 2;     // 0..124

    const int ty = tid >> 4;              // 0..15
    const int tx = tid & 15;              // 0..15

    const float* Asrc = (MODE == 0) ? A : (const float*)g_Y;

    float acc[8][8];
#pragma unroll
    for (int i = 0; i < 8; i++)
#pragma unroll
        for (int j = 0; j < 8; j++) acc[i][j] = 0.f;

    const float* Ab = Asrc + (size_t)row0 * K_DIM;
    const float* Wb = W + col0;

    for (int k0 = 0; k0 < K_DIM; k0 += 16) {
#pragma unroll
        for (int i = 0; i < 2; i++) {
            int r = aRow + i * 64;
            float4 v = *(const float4*)(Ab + (size_t)r * K_DIM + (k0 + aCol));
            As[aCol + 0][r] = v.x;
            As[aCol + 1][r] = v.y;
            As[aCol + 2][r] = v.z;
            As[aCol + 3][r] = v.w;
        }
#pragma unroll
        for (int i = 0; i < 2; i++) {
            int r = bRow + i * 8;
            *(float4*)&Bs[r][bCol] = *(const float4*)(Wb + (size_t)(k0 + r) * N + bCol);
        }
        __syncthreads();

#pragma unroll
        for (int kk = 0; kk < 16; kk++) {
            float regM[8], regN[8];
            *(float4*)&regM[0] = *(float4*)&As[kk][ty * 8];
            *(float4*)&regM[4] = *(float4*)&As[kk][ty * 8 + 4];
            *(float4*)&regN[0] = *(float4*)&Bs[kk][tx * 8];
            *(float4*)&regN[4] = *(float4*)&Bs[kk][tx * 8 + 4];
#pragma unroll
            for (int i = 0; i < 8; i++)
#pragma unroll
                for (int j = 0; j < 8; j++)
                    acc[i][j] = fmaf(regM[i], regN[j], acc[i][j]);
        }
        __syncthreads();
    }

    float bv[8];
#pragma unroll
    for (int j = 0; j < 8; j++) bv[j] = bias[col0 + tx * 8 + j];

    if (MODE == 0) {
        // scatter qkv -> g_Q/g_K/g_V in [bh][t][d]
#pragma unroll
        for (int i = 0; i < 8; i++) {
            int r = row0 + ty * 8 + i;
            int b = r >> 11;           // /2048
            int t = r & 2047;
#pragma unroll
            for (int j = 0; j < 8; j++) {
                int c = col0 + tx * 8 + j;
                float v = acc[i][j] + bv[j];
                int which = c >> 10;   // 0=Q 1=K 2=V (uniform per CTA)
                int n = c & 1023;
                int h = n >> 6;
                int d = n & 63;
                size_t idx = (((size_t)(b * NH + h) * T_SEQ) + t) * DH + d;
                float* dst = (which == 0) ? g_Q : (which == 1) ? g_K : g_V;
                dst[idx] = v;
            }
        }
    } else {
#pragma unroll
        for (int i = 0; i < 8; i++) {
            size_t r = row0 + ty * 8 + i;
#pragma unroll
            for (int j = 0; j < 8; j++) {
                int c = col0 + tx * 8 + j;
                Cout[r * N + c] = acc[i][j] + bv[j];
            }
        }
    }
}

// ---------------------------------------------------------------------------
// Causal flash attention, fp32. One CTA per (bh, 64-query tile).
// 256 threads: ty=tid/16 owns 4 query rows, tx=tid%16 owns 4 cols.
// Online softmax; key blocks of 64 up to the causal limit.
// Dynamic smem: Qt[64][68] (d-major), Kt[64][68] (d-major), Vs[64][68], Pt[64][68]
// ---------------------------------------------------------------------------
#define APAD 68
#define ABUF (DH * APAD)                           // floats per buffer
#define ATTN_SMEM (4 * ABUF * (int)sizeof(float))  // 69632 bytes

__global__ __launch_bounds__(256, 3)
void attn_kernel()
{
    extern __shared__ float smem[];
    float* Qt = smem;               // [d][q]
    float* Kt = smem + ABUF;        // [d][k]
    float* Vs = smem + 2 * ABUF;    // [k][d]
    float* Pt = smem + 3 * ABUF;    // [k][q]

    const int tid = threadIdx.x;
    const int qb  = blockIdx.x;     // 0..31
    const int bh  = blockIdx.y;     // 0..63
    const int q0  = qb * 64;

    const float* Qg = g_Q + (size_t)bh * T_SEQ * DH;
    const float* Kg = g_K + (size_t)bh * T_SEQ * DH;
    const float* Vg = g_V + (size_t)bh * T_SEQ * DH;

    // Load Q tile transposed, pre-scaled by 1/sqrt(Dh)=0.125
#pragma unroll
    for (int it = 0; it < 4; it++) {
        int s   = tid + it * 256;    // float4 slot 0..1023
        int row = s >> 4;            // query 0..63
        int c4  = (s & 15) << 2;     // dim 0..60
        float4 v = *(const float4*)(Qg + (size_t)(q0 + row) * DH + c4);
        Qt[(c4 + 0) * APAD + row] = v.x * 0.125f;
        Qt[(c4 + 1) * APAD + row] = v.y * 0.125f;
        Qt[(c4 + 2) * APAD + row] = v.z * 0.125f;
        Qt[(c4 + 3) * APAD + row] = v.w * 0.125f;
    }

    const int ty = tid >> 4;   // q rows ty*4..+4
    const int tx = tid & 15;   // cols tx*4..+4

    float acc[4][4];
    float mrow[4], lrow[4];
#pragma unroll
    for (int i = 0; i < 4; i++) {
        mrow[i] = -1e30f;
        lrow[i] = 0.f;
#pragma unroll
        for (int j = 0; j < 4; j++) acc[i][j] = 0.f;
    }

    for (int jb = 0; jb <= qb; jb++) {
        const int k0 = jb * 64;
        __syncthreads();   // previous PV (reads Vs/Pt) done before reload
#pragma unroll
        for (int it = 0; it < 4; it++) {
            int s   = tid + it * 256;
            int row = s >> 4;
            int c4  = (s & 15) << 2;
            float4 kv = *(const float4*)(Kg + (size_t)(k0 + row) * DH + c4);
            Kt[(c4 + 0) * APAD + row] = kv.x;
            Kt[(c4 + 1) * APAD + row] = kv.y;
            Kt[(c4 + 2) * APAD + row] = kv.z;
            Kt[(c4 + 3) * APAD + row] = kv.w;
            *(float4*)&Vs[row * APAD + c4] =
                *(const float4*)(Vg + (size_t)(k0 + row) * DH + c4);
        }
        __syncthreads();

        // S[4q][4k] = Q K^T (scale already folded into Q)
        float S[4][4];
#pragma unroll
        for (int i = 0; i < 4; i++)
#pragma unroll
            for (int j = 0; j < 4; j++) S[i][j] = 0.f;

#pragma unroll 16
        for (int d = 0; d < DH; d++) {
            float4 qv = *(float4*)&Qt[d * APAD + ty * 4];
            float4 kv = *(float4*)&Kt[d * APAD + tx * 4];
            float qr[4] = {qv.x, qv.y, qv.z, qv.w};
            float kr[4] = {kv.x, kv.y, kv.z, kv.w};
#pragma unroll
            for (int i = 0; i < 4; i++)
#pragma unroll
                for (int j = 0; j < 4; j++)
                    S[i][j] = fmaf(qr[i], kr[j], S[i][j]);
        }

        if (jb == qb) {   // diagonal block: causal mask
#pragma unroll
            for (int i = 0; i < 4; i++)
#pragma unroll
                for (int j = 0; j < 4; j++)
                    if ((k0 + tx * 4 + j) > (q0 + ty * 4 + i)) S[i][j] = -1e30f;
        }

        // Online softmax. Row = 16 threads (same ty) = one 16-lane shfl segment.
#pragma unroll
        for (int i = 0; i < 4; i++) {
            float m = fmaxf(fmaxf(S[i][0], S[i][1]), fmaxf(S[i][2], S[i][3]));
            m = fmaxf(m, __shfl_xor_sync(0xffffffffu, m, 8));
            m = fmaxf(m, __shfl_xor_sync(0xffffffffu, m, 4));
            m = fmaxf(m, __shfl_xor_sync(0xffffffffu, m, 2));
            m = fmaxf(m, __shfl_xor_sync(0xffffffffu, m, 1));
            float mnew = fmaxf(mrow[i], m);
            float corr = __expf(mrow[i] - mnew);
            mrow[i] = mnew;

            float ls = 0.f;
#pragma unroll
            for (int j = 0; j < 4; j++) {
                float p = __expf(S[i][j] - mnew);
                S[i][j] = p;
                ls += p;
            }
            ls += __shfl_xor_sync(0xffffffffu, ls, 8);
            ls += __shfl_xor_sync(0xffffffffu, ls, 4);
            ls += __shfl_xor_sync(0xffffffffu, ls, 2);
            ls += __shfl_xor_sync(0xffffffffu, ls, 1);
            lrow[i] = lrow[i] * corr + ls;

#pragma unroll
            for (int j = 0; j < 4; j++) {
                acc[i][j] *= corr;
                Pt[(tx * 4 + j) * APAD + ty * 4 + i] = S[i][j];
            }
        }
        __syncthreads();

        // O[4q][4d] += P @ V
#pragma unroll 16
        for (int k = 0; k < 64; k++) {
            float4 pv = *(float4*)&Pt[k * APAD + ty * 4];
            float4 vv = *(float4*)&Vs[k * APAD + tx * 4];
            float pr[4] = {pv.x, pv.y, pv.z, pv.w};
            float vr[4] = {vv.x, vv.y, vv.z, vv.w};
#pragma unroll
            for (int i = 0; i < 4; i++)
#pragma unroll
                for (int j = 0; j < 4; j++)
                    acc[i][j] = fmaf(pr[i], vr[j], acc[i][j]);
        }
    }

    // Epilogue: y[b][t][h*64+d] = acc / l
    const int b = bh >> 4;
    const int h = bh & 15;
#pragma unroll
    for (int i = 0; i < 4; i++) {
        float inv = 1.f / lrow[i];
        size_t t = (size_t)q0 + ty * 4 + i;
#pragma unroll
        for (int j = 0; j < 4; j++) {
            g_Y[((size_t)b * T_SEQ + t) * NDIM + h * DH + tx * 4 + j] =
                acc[i][j] * inv;
        }
    }
}

// ---------------------------------------------------------------------------
extern "C" void kernel_launch(void* const* d_in, const int* in_sizes, int n_in,
                              void* d_out, int out_size)
{
    (void)in_sizes; (void)n_in; (void)out_size;
    const float* x      = (const float*)d_in[0];   // [4,2048,1024]
    const float* W_attn = (const float*)d_in[1];   // [1024,3072]
    const float* b_attn = (const float*)d_in[2];   // [3072]
    const float* W_proj = (const float*)d_in[3];   // [1024,1024]
    const float* b_proj = (const float*)d_in[4];   // [1024]
    float* out = (float*)d_out;                    // [4,2048,1024]

    // Host-side attribute set (not a stream op — capture-safe, idempotent)
    cudaFuncSetAttribute(attn_kernel,
                         cudaFuncAttributeMaxDynamicSharedMemorySize, ATTN_SMEM);

    // 1) QKV GEMM + scatter to [bh][t][d]
    sgemm_kernel<3072, 0><<<dim3(3072 / 128, M_ROWS / 128), 256>>>(
        x, W_attn, b_attn, nullptr);

    // 2) Causal flash attention
    attn_kernel<<<dim3(T_SEQ / 64, BH_TOT), 256, ATTN_SMEM>>>();

    // 3) Output projection
    sgemm_kernel<1024, 1><<<dim3(1024 / 128, M_ROWS / 128), 256>>>(
        nullptr, W_proj, b_proj, out);
}

// round 12
// speedup vs baseline: 1.4014x; 1.3877x over previous
#include <cuda_runtime.h>
#include <cuda_bf16.h>
#include <cstdint>

// Problem shape (fixed by reference): B=4, T=2048, N=1024, H=16, Dh=64
#define B_SZ   4
#define T_SEQ  2048
#define NDIM   1024
#define NH     16
#define DH     64
#define BH_TOT (B_SZ * NH)          // 64
#define M_ROWS (B_SZ * T_SEQ)       // 8192
#define K_DIM  1024

// Scratch (device globals — allocation-free per harness rules).
__device__ float g_Q[(size_t)BH_TOT * T_SEQ * DH];   // [bh][t][d]
__device__ float g_K[(size_t)BH_TOT * T_SEQ * DH];
__device__ float g_V[(size_t)BH_TOT * T_SEQ * DH];
__device__ float g_Y[(size_t)M_ROWS * NDIM];         // attention output [b*T+t][n]

// ---------------------------------------------------------------------------
// PTX helpers: ldmatrix + bf16 mma (fp32 accumulate)
// ---------------------------------------------------------------------------
__device__ __forceinline__ uint32_t smem_u32(const void* p) {
    return (uint32_t)__cvta_generic_to_shared(p);
}
__device__ __forceinline__ void ldsm_x4(uint32_t& r0, uint32_t& r1,
                                        uint32_t& r2, uint32_t& r3, uint32_t addr) {
    asm volatile("ldmatrix.sync.aligned.m8n8.x4.shared.b16 {%0,%1,%2,%3}, [%4];"
                 : "=r"(r0), "=r"(r1), "=r"(r2), "=r"(r3) : "r"(addr));
}
__device__ __forceinline__ void ldsm_x2_trans(uint32_t& r0, uint32_t& r1, uint32_t addr) {
    asm volatile("ldmatrix.sync.aligned.m8n8.x2.trans.shared.b16 {%0,%1}, [%2];"
                 : "=r"(r0), "=r"(r1) : "r"(addr));
}
__device__ __forceinline__ void mma16816(float* c, const uint32_t* a,
                                         uint32_t b0, uint32_t b1) {
    asm volatile(
        "mma.sync.aligned.m16n8k16.row.col.f32.bf16.bf16.f32 "
        "{%0,%1,%2,%3}, {%4,%5,%6,%7}, {%8,%9}, {%0,%1,%2,%3};"
        : "+f"(c[0]), "+f"(c[1]), "+f"(c[2]), "+f"(c[3])
        : "r"(a[0]), "r"(a[1]), "r"(a[2]), "r"(a[3]), "r"(b0), "r"(b1));
}

// fp32 pair -> (hi bf16x2, lo bf16x2), lo = residual
__device__ __forceinline__ void split2(float x, float y, uint32_t& hi, uint32_t& lo) {
    __nv_bfloat16 hx = __float2bfloat16(x);
    __nv_bfloat16 hy = __float2bfloat16(y);
    __nv_bfloat162 h; h.x = hx; h.y = hy;
    __nv_bfloat162 l = __floats2bfloat162_rn(x - __bfloat162float(hx),
                                             y - __bfloat162float(hy));
    hi = *reinterpret_cast<uint32_t*>(&h);
    lo = *reinterpret_cast<uint32_t*>(&l);
}

__device__ __forceinline__ void store_qkv(int r, int c, float v) {
    int b = r >> 11;               // /2048
    int t = r & 2047;
    int which = c >> 10;           // 0=Q 1=K 2=V
    int n = c & 1023;
    int h = n >> 6;
    int d = n & 63;
    float* dst = (which == 0) ? g_Q : (which == 1) ? g_K : g_V;
    dst[(((size_t)(b * NH + h) * T_SEQ) + t) * DH + d] = v;
}

// ---------------------------------------------------------------------------
// Tensor-core GEMM with bf16 hi/lo split (3-term compensated product).
// C[M=8192, N] = A[8192,1024] @ W[1024,N] + bias
// MODE 0: A = x param, epilogue scatters into g_Q/g_K/g_V
// MODE 1: A = g_Y,    epilogue writes Cout row-major
// CTA tile 128x128, BK=32, 256 threads (8 warps, each 64x32).
// ---------------------------------------------------------------------------
#define LDA 40    // halves per A smem row (32 + 8 pad) -> conflict-free ldmatrix
#define LDB 136   // halves per B smem row (128 + 8 pad)

template <int N, int MODE>
__global__ __launch_bounds__(256, 2)
void mma_gemm(const float* __restrict__ A, const float* __restrict__ W,
              const float* __restrict__ bias, float* __restrict__ Cout)
{
    __shared__ __nv_bfloat16 As_hi[128 * LDA];
    __shared__ __nv_bfloat16 As_lo[128 * LDA];
    __shared__ __nv_bfloat16 Bs_hi[32 * LDB];
    __shared__ __nv_bfloat16 Bs_lo[32 * LDB];

    const int tid  = threadIdx.x;
    const int lane = tid & 31;
    const int warp = tid >> 5;
    const int wm   = warp & 1;    // 0..1 -> row block of 64
    const int wn   = warp >> 1;   // 0..3 -> col block of 32
    const int row0 = blockIdx.y * 128;
    const int col0 = blockIdx.x * 128;

    const float* Asrc = (MODE == 0) ? A : (const float*)g_Y;

    float acc[4][4][4];
#pragma unroll
    for (int mt = 0; mt < 4; mt++)
#pragma unroll
        for (int nt = 0; nt < 4; nt++)
#pragma unroll
            for (int e = 0; e < 4; e++) acc[mt][nt][e] = 0.f;

    // fill-phase indices
    const int arow = tid >> 1;            // 0..127
    const int ac0  = (tid & 1) * 16;      // 0 or 16
    const int brow = tid >> 3;            // 0..31
    const int bc0  = (tid & 7) * 16;      // 0..112

    // ldmatrix base addresses (bytes, shared space)
    const int a_r = lane & 15;
    const int a_c = (lane >> 4) << 3;
    const uint32_t a_hi_base = smem_u32(&As_hi[(wm * 64 + a_r) * LDA + a_c]);
    const uint32_t a_lo_base = smem_u32(&As_lo[(wm * 64 + a_r) * LDA + a_c]);
    const int b_k = lane & 15;
    const uint32_t b_hi_base = smem_u32(&Bs_hi[b_k * LDB + wn * 32]);
    const uint32_t b_lo_base = smem_u32(&Bs_lo[b_k * LDB + wn * 32]);

    const float* ap = Asrc + (size_t)(row0 + arow) * K_DIM + ac0;
    const float* bp = W + (size_t)brow * N + col0 + bc0;

#pragma unroll 1
    for (int k0 = 0; k0 < K_DIM; k0 += 32) {
        // ---- fill A tile (fp32 -> hi/lo bf16) ----
#pragma unroll
        for (int j = 0; j < 4; j++) {
            float4 v = *(const float4*)(ap + k0 + j * 4);
            uint32_t h0, l0, h1, l1;
            split2(v.x, v.y, h0, l0);
            split2(v.z, v.w, h1, l1);
            int off = arow * LDA + ac0 + j * 4;
            *(uint2*)&As_hi[off] = make_uint2(h0, h1);
            *(uint2*)&As_lo[off] = make_uint2(l0, l1);
        }
        // ---- fill B tile ----
#pragma unroll
        for (int j = 0; j < 4; j++) {
            float4 v = *(const float4*)(bp + (size_t)k0 * N + j * 4);
            uint32_t h0, l0, h1, l1;
            split2(v.x, v.y, h0, l0);
            split2(v.z, v.w, h1, l1);
            int off = brow * LDB + bc0 + j * 4;
            *(uint2*)&Bs_hi[off] = make_uint2(h0, h1);
            *(uint2*)&Bs_lo[off] = make_uint2(l0, l1);
        }
        __syncthreads();

        // ---- MMA phase: two k16 steps ----
#pragma unroll
        for (int ks = 0; ks < 2; ks++) {
            uint32_t bh[4][2], bl[4][2];
#pragma unroll
            for (int nt = 0; nt < 4; nt++) {
                uint32_t boff = (uint32_t)((ks * 16) * LDB + nt * 8) * 2u;
                ldsm_x2_trans(bh[nt][0], bh[nt][1], b_hi_base + boff);
                ldsm_x2_trans(bl[nt][0], bl[nt][1], b_lo_base + boff);
            }
#pragma unroll
            for (int mt = 0; mt < 4; mt++) {
                uint32_t ah[4], al[4];
                uint32_t aoff = (uint32_t)(mt * 16 * LDA + ks * 16) * 2u;
                ldsm_x4(ah[0], ah[1], ah[2], ah[3], a_hi_base + aoff);
                ldsm_x4(al[0], al[1], al[2], al[3], a_lo_base + aoff);
#pragma unroll
                for (int nt = 0; nt < 4; nt++) {
                    mma16816(acc[mt][nt], ah, bh[nt][0], bh[nt][1]);  // hi*hi
                    mma16816(acc[mt][nt], ah, bl[nt][0], bl[nt][1]);  // hi*lo
                    mma16816(acc[mt][nt], al, bh[nt][0], bh[nt][1]);  // lo*hi
                }
            }
        }
        __syncthreads();
    }

    // ---- epilogue ----
    const int r_lane = lane >> 2;          // 0..7
    const int c_lane = (lane & 3) * 2;     // 0,2,4,6
#pragma unroll
    for (int mt = 0; mt < 4; mt++) {
#pragma unroll
        for (int nt = 0; nt < 4; nt++) {
            int c = col0 + wn * 32 + nt * 8 + c_lane;
            float b0 = bias[c], b1 = bias[c + 1];
#pragma unroll
            for (int h2 = 0; h2 < 2; h2++) {
                int r = row0 + wm * 64 + mt * 16 + r_lane + h2 * 8;
                float v0 = acc[mt][nt][h2 * 2 + 0] + b0;
                float v1 = acc[mt][nt][h2 * 2 + 1] + b1;
                if (MODE == 0) {
                    store_qkv(r, c, v0);
                    store_qkv(r, c + 1, v1);
                } else {
                    Cout[(size_t)r * N + c]     = v0;
                    Cout[(size_t)r * N + c + 1] = v1;
                }
            }
        }
    }
}

// ---------------------------------------------------------------------------
// Causal flash attention, fp32 (unchanged from best passing kernel).
// ---------------------------------------------------------------------------
#define APAD 68
#define ABUF (DH * APAD)
#define ATTN_SMEM (4 * ABUF * (int)sizeof(float))

__global__ __launch_bounds__(256, 3)
void attn_kernel()
{
    extern __shared__ float smem[];
    float* Qt = smem;               // [d][q]
    float* Kt = smem + ABUF;        // [d][k]
    float* Vs = smem + 2 * ABUF;    // [k][d]
    float* Pt = smem + 3 * ABUF;    // [k][q]

    const int tid = threadIdx.x;
    const int qb  = blockIdx.x;
    const int bh  = blockIdx.y;
    const int q0  = qb * 64;

    const float* Qg = g_Q + (size_t)bh * T_SEQ * DH;
    const float* Kg = g_K + (size_t)bh * T_SEQ * DH;
    const float* Vg = g_V + (size_t)bh * T_SEQ * DH;

#pragma unroll
    for (int it = 0; it < 4; it++) {
        int s   = tid + it * 256;
        int row = s >> 4;
        int c4  = (s & 15) << 2;
        float4 v = *(const float4*)(Qg + (size_t)(q0 + row) * DH + c4);
        Qt[(c4 + 0) * APAD + row] = v.x * 0.125f;
        Qt[(c4 + 1) * APAD + row] = v.y * 0.125f;
        Qt[(c4 + 2) * APAD + row] = v.z * 0.125f;
        Qt[(c4 + 3) * APAD + row] = v.w * 0.125f;
    }

    const int ty = tid >> 4;
    const int tx = tid & 15;

    float acc[4][4];
    float mrow[4], lrow[4];
#pragma unroll
    for (int i = 0; i < 4; i++) {
        mrow[i] = -1e30f;
        lrow[i] = 0.f;
#pragma unroll
        for (int j = 0; j < 4; j++) acc[i][j] = 0.f;
    }

    for (int jb = 0; jb <= qb; jb++) {
        const int k0 = jb * 64;
        __syncthreads();
#pragma unroll
        for (int it = 0; it < 4; it++) {
            int s   = tid + it * 256;
            int row = s >> 4;
            int c4  = (s & 15) << 2;
            float4 kv = *(const float4*)(Kg + (size_t)(k0 + row) * DH + c4);
            Kt[(c4 + 0) * APAD + row] = kv.x;
            Kt[(c4 + 1) * APAD + row] = kv.y;
            Kt[(c4 + 2) * APAD + row] = kv.z;
            Kt[(c4 + 3) * APAD + row] = kv.w;
            *(float4*)&Vs[row * APAD + c4] =
                *(const float4*)(Vg + (size_t)(k0 + row) * DH + c4);
        }
        __syncthreads();

        float S[4][4];
#pragma unroll
        for (int i = 0; i < 4; i++)
#pragma unroll
            for (int j = 0; j < 4; j++) S[i][j] = 0.f;

#pragma unroll 16
        for (int d = 0; d < DH; d++) {
            float4 qv = *(float4*)&Qt[d * APAD + ty * 4];
            float4 kv = *(float4*)&Kt[d * APAD + tx * 4];
            float qr[4] = {qv.x, qv.y, qv.z, qv.w};
            float kr[4] = {kv.x, kv.y, kv.z, kv.w};
#pragma unroll
            for (int i = 0; i < 4; i++)
#pragma unroll
                for (int j = 0; j < 4; j++)
                    S[i][j] = fmaf(qr[i], kr[j], S[i][j]);
        }

        if (jb == qb) {
#pragma unroll
            for (int i = 0; i < 4; i++)
#pragma unroll
                for (int j = 0; j < 4; j++)
                    if ((k0 + tx * 4 + j) > (q0 + ty * 4 + i)) S[i][j] = -1e30f;
        }

#pragma unroll
        for (int i = 0; i < 4; i++) {
            float m = fmaxf(fmaxf(S[i][0], S[i][1]), fmaxf(S[i][2], S[i][3]));
            m = fmaxf(m, __shfl_xor_sync(0xffffffffu, m, 8));
            m = fmaxf(m, __shfl_xor_sync(0xffffffffu, m, 4));
            m = fmaxf(m, __shfl_xor_sync(0xffffffffu, m, 2));
            m = fmaxf(m, __shfl_xor_sync(0xffffffffu, m, 1));
            float mnew = fmaxf(mrow[i], m);
            float corr = __expf(mrow[i] - mnew);
            mrow[i] = mnew;

            float ls = 0.f;
#pragma unroll
            for (int j = 0; j < 4; j++) {
                float p = __expf(S[i][j] - mnew);
                S[i][j] = p;
                ls += p;
            }
            ls += __shfl_xor_sync(0xffffffffu, ls, 8);
            ls += __shfl_xor_sync(0xffffffffu, ls, 4);
            ls += __shfl_xor_sync(0xffffffffu, ls, 2);
            ls += __shfl_xor_sync(0xffffffffu, ls, 1);
            lrow[i] = lrow[i] * corr + ls;

#pragma unroll
            for (int j = 0; j < 4; j++) {
                acc[i][j] *= corr;
                Pt[(tx * 4 + j) * APAD + ty * 4 + i] = S[i][j];
            }
        }
        __syncthreads();

#pragma unroll 16
        for (int k = 0; k < 64; k++) {
            float4 pv = *(float4*)&Pt[k * APAD + ty * 4];
            float4 vv = *(float4*)&Vs[k * APAD + tx * 4];
            float pr[4] = {pv.x, pv.y, pv.z, pv.w};
            float vr[4] = {vv.x, vv.y, vv.z, vv.w};
#pragma unroll
            for (int i = 0; i < 4; i++)
#pragma unroll
                for (int j = 0; j < 4; j++)
                    acc[i][j] = fmaf(pr[i], vr[j], acc[i][j]);
        }
    }

    const int b = bh >> 4;
    const int h = bh & 15;
#pragma unroll
    for (int i = 0; i < 4; i++) {
        float inv = 1.f / lrow[i];
        size_t t = (size_t)q0 + ty * 4 + i;
#pragma unroll
        for (int j = 0; j < 4; j++) {
            g_Y[((size_t)b * T_SEQ + t) * NDIM + h * DH + tx * 4 + j] =
                acc[i][j] * inv;
        }
    }
}

// ---------------------------------------------------------------------------
extern "C" void kernel_launch(void* const* d_in, const int* in_sizes, int n_in,
                              void* d_out, int out_size)
{
    (void)in_sizes; (void)n_in; (void)out_size;
    const float* x      = (const float*)d_in[0];   // [4,2048,1024]
    const float* W_attn = (const float*)d_in[1];   // [1024,3072]
    const float* b_attn = (const float*)d_in[2];   // [3072]
    const float* W_proj = (const float*)d_in[3];   // [1024,1024]
    const float* b_proj = (const float*)d_in[4];   // [1024]
    float* out = (float*)d_out;                    // [4,2048,1024]

    cudaFuncSetAttribute(attn_kernel,
                         cudaFuncAttributeMaxDynamicSharedMemorySize, ATTN_SMEM);

    // 1) QKV GEMM (tensor cores, bf16 split) + scatter to [bh][t][d]
    mma_gemm<3072, 0><<<dim3(3072 / 128, M_ROWS / 128), 256>>>(
        x, W_attn, b_attn, nullptr);

    // 2) Causal flash attention
    attn_kernel<<<dim3(T_SEQ / 64, BH_TOT), 256, ATTN_SMEM>>>();

    // 3) Output projection (tensor cores, bf16 split)
    mma_gemm<1024, 1><<<dim3(1024 / 128, M_ROWS / 128), 256>>>(
        nullptr, W_proj, b_proj, out);
}